// round 15
// baseline (speedup 1.0000x reference)
#include <cuda_runtime.h>
#include <cuda_bf16.h>
#include <cstdint>

// ---------------- problem constants ----------------
#define B_      32
#define E_      5
#define CIN_    256
#define COUT_   256
#define HH      56
#define WW      56
#define HW      (HH * WW)        // 3136
#define M_PER_OC 2304
#define NP      3364             // 58*58 padded pixels
#define KCH     108              // 12 groups x 9 shifts
#define NTILES  13               // n tiles of 256 px
#define NPHASE  60               // 12 groups x 5 phases (2,2,2,2,1 chunks)

// SMEM: 6 A-stages + 2 B super-tiles, 1 CTA/SM
#define A_TILE_B   16384         // 128 rows * 128B
#define NSTAGE_A   6
#define BSUP_ROWS  374           // 256 + max shift 118
#define BSUP_B     49152         // 384 rows * 128B (padded)
#define BBUF_OFF   (NSTAGE_A * A_TILE_B)          // 98304
#define SMEM_TOTAL (BBUF_OFF + 2 * BSUP_B)        // 196608 (192 KB)

typedef unsigned long long u64;

// ---------------- device globals ----------------
__device__ int g_expert[B_];
// A matrix: [e][ocb][128 oc][6912 k], k = ((cq*3+kb)*9 + k1k2)*64 + cl
__device__ __nv_bfloat16 g_A[(size_t)E_ * 2 * 128 * 6912];
// padded transposed input: [b][n 3364][c 512] (c: 0-255 hi, 256-511 lo)
__device__ __nv_bfloat16 g_xpt[(size_t)B_ * NP * 512];

// ---------------- helpers ----------------
__device__ __forceinline__ unsigned SWZ(unsigned off) {
    return off ^ ((off >> 3) & 0x70);
}

__device__ __forceinline__ void cpa16(unsigned dst, const void* src, unsigned srcsize) {
    asm volatile("cp.async.ca.shared.global [%0], [%1], 16, %2;\n"
                 :: "r"(dst), "l"(src), "r"(srcsize) : "memory");
}

__device__ __forceinline__ void ldsm_x4(unsigned* r, unsigned addr) {
    asm volatile("ldmatrix.sync.aligned.m8n8.x4.shared.b16 {%0,%1,%2,%3}, [%4];"
                 : "=r"(r[0]), "=r"(r[1]), "=r"(r[2]), "=r"(r[3]) : "r"(addr));
}

__device__ __forceinline__ void mma_bf16(float* d, const unsigned* a,
                                         unsigned b0, unsigned b1) {
    asm volatile(
        "mma.sync.aligned.m16n8k16.row.col.f32.bf16.bf16.f32 "
        "{%0,%1,%2,%3}, {%4,%5,%6,%7}, {%8,%9}, {%0,%1,%2,%3};"
        : "+f"(d[0]), "+f"(d[1]), "+f"(d[2]), "+f"(d[3])
        : "r"(a[0]), "r"(a[1]), "r"(a[2]), "r"(a[3]), "r"(b0), "r"(b1));
}

// ---------------------------------------------------------------------------
// Kernel 1: top-1 expert per sample
// ---------------------------------------------------------------------------
__global__ void expert_kernel(const float* __restrict__ scores) {
    int b = threadIdx.x;
    if (b < B_) {
        const float* s = scores + b * E_;
        float best = s[0];
        int bi = 0;
#pragma unroll
        for (int e = 1; e < E_; ++e) {
            float v = s[e];
            if (v > best) { best = v; bi = e; }
        }
        g_expert[b] = bi;
    }
}

// ---------------------------------------------------------------------------
// Kernel 2: build A (agg weight -> bf16 hi/lo, GROUP-major K layout)
// ---------------------------------------------------------------------------
__global__ void abuild_kernel(const float* __restrict__ weight,
                              const float* __restrict__ lora_A,
                              const float* __restrict__ lora_B) {
    int t = blockIdx.x * blockDim.x + threadIdx.x;   // 5*256*2304
    int m    = t % M_PER_OC;
    int rest = t / M_PER_OC;
    int oc   = rest % COUT_;
    int e    = rest / COUT_;
    if (e >= E_) return;

    int j = m / 768, v = m % 768;
    const float* Bp = lora_B + e * 9216 + (3 * oc + j) * 12;
    const float* Ap = lora_A + e * 9216;
    float acc = 0.f;
#pragma unroll
    for (int r = 0; r < 12; ++r) acc += Bp[r] * Ap[r * 768 + v];
    float val = weight[oc * M_PER_OC + m] + 4.0f * acc;

    __nv_bfloat16 hi = __float2bfloat16(val);
    __nv_bfloat16 lo = __float2bfloat16(val - __bfloat162float(hi));

    int ci = m / 9, kk = m % 9;          // kk = k1*3+k2
    int ocb = oc >> 7, ocl = oc & 127;
    int cq = ci >> 6, cl = ci & 63;
    __nv_bfloat16* arow = g_A + ((size_t)(e * 2 + ocb) * 128 + ocl) * 6912;
    arow[((cq * 3 + 0) * 9 + kk) * 64 + cl] = hi;   // pairs x_hi
    arow[((cq * 3 + 1) * 9 + kk) * 64 + cl] = hi;   // pairs x_lo
    arow[((cq * 3 + 2) * 9 + kk) * 64 + cl] = lo;   // pairs x_hi
}

// ---------------------------------------------------------------------------
// Kernel 3: padded, transposed, bf16-split input xp_t[b][n][c]
// ---------------------------------------------------------------------------
__global__ void xprep_kernel(const float* __restrict__ x) {
    __shared__ float tile[64 * 58];
    int cblk = blockIdx.x, y58 = blockIdx.y, b = blockIdx.z;
    int tid = threadIdx.x;
    int y = y58 - 1;
    if (y >= 0 && y < HH) {
        for (int idx = tid; idx < 64 * 58; idx += 256) {
            int c = idx / 58, px = idx % 58;
            int xx = px - 1;
            float v = 0.f;
            if (xx >= 0 && xx < WW)
                v = x[((size_t)(b * CIN_ + cblk * 64 + c)) * HW + y * WW + xx];
            tile[idx] = v;
        }
    } else {
        for (int idx = tid; idx < 64 * 58; idx += 256) tile[idx] = 0.f;
    }
    __syncthreads();
    __nv_bfloat16* dst = g_xpt + ((size_t)b * NP + y58 * 58) * 512 + cblk * 64;
    for (int idx = tid; idx < 58 * 64; idx += 256) {
        int px = idx >> 6, c = idx & 63;
        float v = tile[c * 58 + px];
        __nv_bfloat16 hi = __float2bfloat16(v);
        __nv_bfloat16 lo = __float2bfloat16(v - __bfloat162float(hi));
        dst[(size_t)px * 512 + c] = hi;
        dst[(size_t)px * 512 + 256 + c] = lo;
    }
}

// ---------------------------------------------------------------------------
// Loaders (512 threads)
// ---------------------------------------------------------------------------
__device__ __forceinline__ void load_A(int q, unsigned abuf,
                                       const __nv_bfloat16* Abase, int tid) {
    int row = tid >> 2;
    int ub  = (tid & 3) * 2;
    const char* arow = (const char*)(Abase + (size_t)row * 6912 + q * 64);
#pragma unroll
    for (int u = 0; u < 2; ++u)
        cpa16(abuf + SWZ(row * 128 + (ub + u) * 16), arow + (ub + u) * 16, 16);
}

__device__ __forceinline__ int group_c0(int g) {
    int cq = g / 3, kb = g % 3;
    return ((kb == 1) ? 256 : 0) + cq * 64;
}

// load 1/3 slice (125 rows) of group gg's B super-tile
__device__ __forceinline__ void load_Bslice3(int gg, int q, unsigned bbuf,
                                             const __nv_bfloat16* Bbase,
                                             int n0, int tid) {
    int c0 = group_c0(gg);
#pragma unroll
    for (int rep = 0; rep < 2; ++rep) {
        int idx = tid + rep * 512;
        if (idx < 125 * 8) {
            int r = q * 125 + (idx >> 3);
            if (r < BSUP_ROWS) {
                int n = n0 + r;
                bool ok = (n < NP);
                const char* src = ok ? (const char*)(Bbase + (size_t)n * 512 + c0)
                                     : (const char*)Bbase;
                unsigned sz = ok ? 16u : 0u;
                cpa16(bbuf + SWZ(r * 128 + (idx & 7) * 16), src + (idx & 7) * 16, sz);
            }
        }
    }
}

// load full B super-tile (prologue)
__device__ __forceinline__ void load_Bfull(int gg, unsigned bbuf,
                                           const __nv_bfloat16* Bbase,
                                           int n0, int tid) {
    int c0 = group_c0(gg);
#pragma unroll
    for (int k = 0; k < 6; ++k) {
        int r = (tid >> 3) + k * 64;
        if (r < BSUP_ROWS) {
            int n = n0 + r;
            bool ok = (n < NP);
            const char* src = ok ? (const char*)(Bbase + (size_t)n * 512 + c0)
                                 : (const char*)Bbase;
            unsigned sz = ok ? 16u : 0u;
            cpa16(bbuf + SWZ(r * 128 + (tid & 7) * 16), src + (tid & 7) * 16, sz);
        }
    }
}

// ---------------------------------------------------------------------------
// Kernel 4: HMMA implicit-GEMM conv. grid (13, 2, 32), 512 threads, 1 CTA/SM.
// CTA: 128 oc x 256 px. Warp grid 4(M)x4(N), warp tile 32x64.
// 60 group-aligned phases, 6-stage A pipeline, B super-tile double-buffered.
// NEW: register double-buffered fragments — LDSM of step s+1 overlaps MMA of s.
// ---------------------------------------------------------------------------
__global__ __launch_bounds__(512, 1)
void conv_mma_kernel(float* __restrict__ out) {
    extern __shared__ __align__(1024) char smem[];
    const unsigned sbase = (unsigned)__cvta_generic_to_shared(smem);
    const int tid  = threadIdx.x;
    const int lane = tid & 31, wid = tid >> 5;
    const int n0   = blockIdx.x * 256;
    const int ocb  = blockIdx.y;
    const int b    = blockIdx.z;
    const int e    = g_expert[b];

    const __nv_bfloat16* Abase = g_A + (size_t)(e * 2 + ocb) * 128 * 6912;
    const __nv_bfloat16* Bbase = g_xpt + (size_t)b * NP * 512;

    unsigned abufs[NSTAGE_A];
#pragma unroll
    for (int i = 0; i < NSTAGE_A; ++i) abufs[i] = sbase + i * A_TILE_B;
    const unsigned bbufs[2] = { sbase + BBUF_OFF, sbase + BBUF_OFF + BSUP_B };

    float acc[64];
#pragma unroll
    for (int i = 0; i < 64; ++i) acc[i] = 0.f;

    // warp / lane geometry: 4(M) x 4(N) warps, warp tile 32(M) x 64(N)
    const int wm = wid & 3, wn = wid >> 2;
    const int m0 = wm * 32, n0w = wn * 64;
    const int g  = lane >> 3, lr = lane & 7;
    const unsigned a_off0 = (unsigned)((m0 + (g & 1) * 8 + lr) * 128 + (g >> 1) * 16);
    const unsigned b_off0 = (unsigned)((n0w + (g >> 1) * 8 + lr) * 128 + (g & 1) * 16);

    // prologue: commit0 = {Bfull(g0), A0, A1}; commit1 = {A2, A3}
    load_Bfull(0, bbufs[0], Bbase, n0, tid);
    load_A(0, abufs[0], Abase, tid);
    load_A(1, abufs[1], Abase, tid);
    asm volatile("cp.async.commit_group;" ::: "memory");
    load_A(2, abufs[2], Abase, tid);
    load_A(3, abufs[3], Abase, tid);
    asm volatile("cp.async.commit_group;" ::: "memory");

    // double-buffered fragments
    unsigned ar[2][8], br[2][16];

#define LOAD_FRAGS(BUF, AB, BSH, KS)                                          \
    do {                                                                      \
        _Pragma("unroll")                                                     \
        for (int mt = 0; mt < 2; ++mt)                                        \
            ldsm_x4(ar[BUF] + mt * 4,                                         \
                    (AB) + SWZ(a_off0 + mt * 2048 + (KS) * 32));              \
        _Pragma("unroll")                                                     \
        for (int ntp = 0; ntp < 4; ++ntp)                                     \
            ldsm_x4(br[BUF] + ntp * 4,                                        \
                    bb + SWZ((BSH) + ntp * 2048 + (KS) * 32));                \
    } while (0)

#define DO_MMAS(BUF)                                                          \
    do {                                                                      \
        _Pragma("unroll")                                                     \
        for (int mt = 0; mt < 2; ++mt)                                        \
            _Pragma("unroll")                                                 \
            for (int nt = 0; nt < 8; ++nt) {                                  \
                int bi = (nt >> 1) * 4 + (nt & 1) * 2;                        \
                mma_bf16(acc + (mt * 8 + nt) * 4, ar[BUF] + mt * 4,           \
                         br[BUF][bi], br[BUF][bi + 1]);                       \
            }                                                                 \
    } while (0)

    for (int p = 0; p < NPHASE; ++p) {
        const int grp = p / 5, q = p - grp * 5;
        const int c0 = 9 * grp + 2 * q;
        const int nc = (q < 4) ? 2 : 1;

        asm volatile("cp.async.wait_group 1;" ::: "memory");
        __syncthreads();

        // prefetch A chunks of phase p+2 and B slice for group grp+1
        if (p + 2 < NPHASE) {
            const int pp = p + 2, g2 = pp / 5, q2 = pp - g2 * 5;
            const int a0 = 9 * g2 + 2 * q2;
            load_A(a0, abufs[a0 % NSTAGE_A], Abase, tid);
            if (q2 < 4)
                load_A(a0 + 1, abufs[(a0 + 1) % NSTAGE_A], Abase, tid);
        }
        if (q < 3 && grp + 1 < 12)
            load_Bslice3(grp + 1, q, bbufs[(grp + 1) & 1], Bbase, n0, tid);
        asm volatile("cp.async.commit_group;" ::: "memory");

        const unsigned bb = bbufs[grp & 1];
        // per-chunk bases for this phase
        unsigned abk[2], bshk[2];
#pragma unroll
        for (int k = 0; k < 2; ++k) {
            int t = c0 + k;
            int jj = t - 9 * grp;
            if (jj > 8) jj = 8;                       // clamp (unused when nc==1)
            abk[k] = abufs[t % NSTAGE_A];
            bshk[k] = b_off0 + ((jj / 3) * 58 + (jj % 3)) * 128;
        }

        if (nc == 2) {
            // 8 flattened steps, software-pipelined fragments
            LOAD_FRAGS(0, abk[0], bshk[0], 0);
#pragma unroll
            for (int s = 0; s < 8; ++s) {
                const int cur = s & 1, nxt = cur ^ 1;
                if (s + 1 < 8)
                    LOAD_FRAGS(nxt, abk[(s + 1) >> 2], bshk[(s + 1) >> 2],
                               (s + 1) & 3);
                DO_MMAS(cur);
            }
        } else {
            LOAD_FRAGS(0, abk[0], bshk[0], 0);
#pragma unroll
            for (int s = 0; s < 4; ++s) {
                const int cur = s & 1, nxt = cur ^ 1;
                if (s + 1 < 4)
                    LOAD_FRAGS(nxt, abk[0], bshk[0], (s + 1) & 3);
                DO_MMAS(cur);
            }
        }
    }

    // --- epilogue: predicated direct stores ---
    const int qrow = lane >> 2;
    const int qc   = (lane & 3) * 2;
    const size_t ob = (size_t)b * COUT_ * HW;
#pragma unroll
    for (int mt = 0; mt < 2; ++mt) {
        const int mA = ocb * 128 + m0 + mt * 16 + qrow;
        const int mB = mA + 8;
#pragma unroll
        for (int nt = 0; nt < 8; ++nt) {
            const float* a4 = acc + (mt * 8 + nt) * 4;
            int p0 = n0 + n0w + nt * 8 + qc;
            int p1 = p0 + 1;
            int y0 = p0 / 58, x0 = p0 % 58;
            int y1 = p1 / 58, x1 = p1 % 58;
            bool v0 = (y0 < HH) && (x0 < WW);
            bool v1 = (y1 < HH) && (x1 < WW);
            if (v0) out[ob + ((size_t)mA * HH + y0) * WW + x0] = a4[0];
            if (v1) out[ob + ((size_t)mA * HH + y1) * WW + x1] = a4[1];
            if (v0) out[ob + ((size_t)mB * HH + y0) * WW + x0] = a4[2];
            if (v1) out[ob + ((size_t)mB * HH + y1) * WW + x1] = a4[3];
        }
    }
}

// ---------------------------------------------------------------------------
extern "C" void kernel_launch(void* const* d_in, const int* in_sizes, int n_in,
                              void* d_out, int out_size) {
    const float* x      = (const float*)d_in[0];
    const float* scores = (const float*)d_in[1];
    const float* weight = (const float*)d_in[2];
    const float* lora_A = (const float*)d_in[3];
    const float* lora_B = (const float*)d_in[4];
    float* out = (float*)d_out;

    cudaFuncSetAttribute(conv_mma_kernel,
                         cudaFuncAttributeMaxDynamicSharedMemorySize, SMEM_TOTAL);

    expert_kernel<<<1, 32>>>(scores);

    int total = E_ * COUT_ * M_PER_OC;          // 2,949,120
    abuild_kernel<<<total / 256, 256>>>(weight, lora_A, lora_B);

    dim3 xg(4, 58, B_);
    xprep_kernel<<<xg, 256>>>(x);

    dim3 cg(NTILES, 2, B_);
    conv_mma_kernel<<<cg, 512, SMEM_TOTAL>>>(out);
}

// round 16
// speedup vs baseline: 1.7000x; 1.7000x over previous
#include <cuda_runtime.h>
#include <cuda_fp16.h>
#include <cstdint>

// ---------------- problem constants ----------------
#define B_      32
#define E_      5
#define CIN_    256
#define COUT_   256
#define HH      56
#define WW      56
#define HW      (HH * WW)        // 3136
#define M_PER_OC 2304
#define NP      3364             // 58*58 padded pixels
#define KCH     36               // 4 groups x 9 shifts (fp16 single: K=2304)
#define NGRP    4
#define NTILES  13               // n tiles of 256 px
#define NPHASE  20               // 4 groups x 5 phases (2,2,2,2,1 chunks)
#define AK      2304             // A row length (fp16 elements)

// SMEM: 6 A-stages + 2 B super-tiles, 1 CTA/SM
#define A_TILE_B   16384         // 128 rows * 128B
#define NSTAGE_A   6
#define BSUP_ROWS  374           // 256 + max shift 118
#define BSUP_B     49152         // 384 rows * 128B (padded)
#define BBUF_OFF   (NSTAGE_A * A_TILE_B)          // 98304
#define SMEM_TOTAL (BBUF_OFF + 2 * BSUP_B)        // 196608 (192 KB)

typedef unsigned long long u64;

// ---------------- device globals ----------------
__device__ int g_expert[B_];
// A matrix: [e][ocb][128 oc][2304 k] fp16, k = (cq*9 + k1k2)*64 + cl
__device__ __half g_A[(size_t)E_ * 2 * 128 * AK];
// padded transposed input: [b][n 3364][c 256] fp16
__device__ __half g_xpt[(size_t)B_ * NP * 256];

// ---------------- helpers ----------------
__device__ __forceinline__ unsigned SWZ(unsigned off) {
    return off ^ ((off >> 3) & 0x70);
}

__device__ __forceinline__ void cpa16(unsigned dst, const void* src, unsigned srcsize) {
    asm volatile("cp.async.ca.shared.global [%0], [%1], 16, %2;\n"
                 :: "r"(dst), "l"(src), "r"(srcsize) : "memory");
}

__device__ __forceinline__ void ldsm_x4(unsigned* r, unsigned addr) {
    asm volatile("ldmatrix.sync.aligned.m8n8.x4.shared.b16 {%0,%1,%2,%3}, [%4];"
                 : "=r"(r[0]), "=r"(r[1]), "=r"(r[2]), "=r"(r[3]) : "r"(addr));
}

__device__ __forceinline__ void mma_f16(float* d, const unsigned* a,
                                        unsigned b0, unsigned b1) {
    asm volatile(
        "mma.sync.aligned.m16n8k16.row.col.f32.f16.f16.f32 "
        "{%0,%1,%2,%3}, {%4,%5,%6,%7}, {%8,%9}, {%0,%1,%2,%3};"
        : "+f"(d[0]), "+f"(d[1]), "+f"(d[2]), "+f"(d[3])
        : "r"(a[0]), "r"(a[1]), "r"(a[2]), "r"(a[3]), "r"(b0), "r"(b1));
}

// ---------------------------------------------------------------------------
// Kernel 1: top-1 expert per sample
// ---------------------------------------------------------------------------
__global__ void expert_kernel(const float* __restrict__ scores) {
    int b = threadIdx.x;
    if (b < B_) {
        const float* s = scores + b * E_;
        float best = s[0];
        int bi = 0;
#pragma unroll
        for (int e = 1; e < E_; ++e) {
            float v = s[e];
            if (v > best) { best = v; bi = e; }
        }
        g_expert[b] = bi;
    }
}

// ---------------------------------------------------------------------------
// Kernel 2: build A (agg weight -> fp16, group-major K layout)
// ---------------------------------------------------------------------------
__global__ void abuild_kernel(const float* __restrict__ weight,
                              const float* __restrict__ lora_A,
                              const float* __restrict__ lora_B) {
    int t = blockIdx.x * blockDim.x + threadIdx.x;   // 5*256*2304
    int m    = t % M_PER_OC;
    int rest = t / M_PER_OC;
    int oc   = rest % COUT_;
    int e    = rest / COUT_;
    if (e >= E_) return;

    int j = m / 768, v = m % 768;
    const float* Bp = lora_B + e * 9216 + (3 * oc + j) * 12;
    const float* Ap = lora_A + e * 9216;
    float acc = 0.f;
#pragma unroll
    for (int r = 0; r < 12; ++r) acc += Bp[r] * Ap[r * 768 + v];
    float val = weight[oc * M_PER_OC + m] + 4.0f * acc;

    int ci = m / 9, kk = m % 9;          // kk = k1*3+k2
    int ocb = oc >> 7, ocl = oc & 127;
    int cq = ci >> 6, cl = ci & 63;
    __half* arow = g_A + ((size_t)(e * 2 + ocb) * 128 + ocl) * AK;
    arow[(cq * 9 + kk) * 64 + cl] = __float2half(val);
}

// ---------------------------------------------------------------------------
// Kernel 3: padded, transposed fp16 input xp_t[b][n][c]
// ---------------------------------------------------------------------------
__global__ void xprep_kernel(const float* __restrict__ x) {
    __shared__ float tile[64 * 58];
    int cblk = blockIdx.x, y58 = blockIdx.y, b = blockIdx.z;
    int tid = threadIdx.x;
    int y = y58 - 1;
    if (y >= 0 && y < HH) {
        for (int idx = tid; idx < 64 * 58; idx += 256) {
            int c = idx / 58, px = idx % 58;
            int xx = px - 1;
            float v = 0.f;
            if (xx >= 0 && xx < WW)
                v = x[((size_t)(b * CIN_ + cblk * 64 + c)) * HW + y * WW + xx];
            tile[idx] = v;
        }
    } else {
        for (int idx = tid; idx < 64 * 58; idx += 256) tile[idx] = 0.f;
    }
    __syncthreads();
    __half* dst = g_xpt + ((size_t)b * NP + y58 * 58) * 256 + cblk * 64;
    for (int idx = tid; idx < 58 * 64; idx += 256) {
        int px = idx >> 6, c = idx & 63;
        dst[(size_t)px * 256 + c] = __float2half(tile[c * 58 + px]);
    }
}

// ---------------------------------------------------------------------------
// Loaders (512 threads)
// ---------------------------------------------------------------------------
__device__ __forceinline__ void load_A(int q, unsigned abuf,
                                       const __half* Abase, int tid) {
    int row = tid >> 2;
    int ub  = (tid & 3) * 2;
    const char* arow = (const char*)(Abase + (size_t)row * AK + q * 64);
#pragma unroll
    for (int u = 0; u < 2; ++u)
        cpa16(abuf + SWZ(row * 128 + (ub + u) * 16), arow + (ub + u) * 16, 16);
}

// load 1/3 slice (125 rows) of group gg's B super-tile
__device__ __forceinline__ void load_Bslice3(int gg, int q, unsigned bbuf,
                                             const __half* Bbase,
                                             int n0, int tid) {
    int c0 = gg * 64;
#pragma unroll
    for (int rep = 0; rep < 2; ++rep) {
        int idx = tid + rep * 512;
        if (idx < 125 * 8) {
            int r = q * 125 + (idx >> 3);
            if (r < BSUP_ROWS) {
                int n = n0 + r;
                bool ok = (n < NP);
                const char* src = ok ? (const char*)(Bbase + (size_t)n * 256 + c0)
                                     : (const char*)Bbase;
                unsigned sz = ok ? 16u : 0u;
                cpa16(bbuf + SWZ(r * 128 + (idx & 7) * 16), src + (idx & 7) * 16, sz);
            }
        }
    }
}

// load full B super-tile (prologue)
__device__ __forceinline__ void load_Bfull(int gg, unsigned bbuf,
                                           const __half* Bbase,
                                           int n0, int tid) {
    int c0 = gg * 64;
#pragma unroll
    for (int k = 0; k < 6; ++k) {
        int r = (tid >> 3) + k * 64;
        if (r < BSUP_ROWS) {
            int n = n0 + r;
            bool ok = (n < NP);
            const char* src = ok ? (const char*)(Bbase + (size_t)n * 256 + c0)
                                 : (const char*)Bbase;
            unsigned sz = ok ? 16u : 0u;
            cpa16(bbuf + SWZ(r * 128 + (tid & 7) * 16), src + (tid & 7) * 16, sz);
        }
    }
}

// ---------------------------------------------------------------------------
// Kernel 4: HMMA implicit-GEMM conv (fp16, K=2304). grid (13, 2, 32), 512 thr.
// CTA: 128 oc x 256 px. Warp grid 4(M)x4(N), warp tile 32x64.
// 20 group-aligned phases, 6-stage A pipeline, B super-tile double-buffered.
// ---------------------------------------------------------------------------
__global__ __launch_bounds__(512, 1)
void conv_mma_kernel(float* __restrict__ out) {
    extern __shared__ __align__(1024) char smem[];
    const unsigned sbase = (unsigned)__cvta_generic_to_shared(smem);
    const int tid  = threadIdx.x;
    const int lane = tid & 31, wid = tid >> 5;
    const int n0   = blockIdx.x * 256;
    const int ocb  = blockIdx.y;
    const int b    = blockIdx.z;
    const int e    = g_expert[b];

    const __half* Abase = g_A + (size_t)(e * 2 + ocb) * 128 * AK;
    const __half* Bbase = g_xpt + (size_t)b * NP * 256;

    unsigned abufs[NSTAGE_A];
#pragma unroll
    for (int i = 0; i < NSTAGE_A; ++i) abufs[i] = sbase + i * A_TILE_B;
    const unsigned bbufs[2] = { sbase + BBUF_OFF, sbase + BBUF_OFF + BSUP_B };

    float acc[64];
#pragma unroll
    for (int i = 0; i < 64; ++i) acc[i] = 0.f;

    // warp / lane geometry: 4(M) x 4(N) warps, warp tile 32(M) x 64(N)
    const int wm = wid & 3, wn = wid >> 2;
    const int m0 = wm * 32, n0w = wn * 64;
    const int g  = lane >> 3, lr = lane & 7;
    const unsigned a_off0 = (unsigned)((m0 + (g & 1) * 8 + lr) * 128 + (g >> 1) * 16);
    const unsigned b_off0 = (unsigned)((n0w + (g >> 1) * 8 + lr) * 128 + (g & 1) * 16);

    // prologue: commit0 = {Bfull(g0), A0, A1}; commit1 = {A2, A3}
    load_Bfull(0, bbufs[0], Bbase, n0, tid);
    load_A(0, abufs[0], Abase, tid);
    load_A(1, abufs[1], Abase, tid);
    asm volatile("cp.async.commit_group;" ::: "memory");
    load_A(2, abufs[2], Abase, tid);
    load_A(3, abufs[3], Abase, tid);
    asm volatile("cp.async.commit_group;" ::: "memory");

    for (int p = 0; p < NPHASE; ++p) {
        const int grp = p / 5, q = p - grp * 5;
        const int c0 = 9 * grp + 2 * q;
        const int nc = (q < 4) ? 2 : 1;

        asm volatile("cp.async.wait_group 1;" ::: "memory");
        __syncthreads();

        // prefetch A chunks of phase p+2 and B slice for group grp+1
        if (p + 2 < NPHASE) {
            const int pp = p + 2, g2 = pp / 5, q2 = pp - g2 * 5;
            const int a0 = 9 * g2 + 2 * q2;
            load_A(a0, abufs[a0 % NSTAGE_A], Abase, tid);
            if (q2 < 4)
                load_A(a0 + 1, abufs[(a0 + 1) % NSTAGE_A], Abase, tid);
        }
        if (q < 3 && grp + 1 < NGRP)
            load_Bslice3(grp + 1, q, bbufs[(grp + 1) & 1], Bbase, n0, tid);
        asm volatile("cp.async.commit_group;" ::: "memory");

        const unsigned bb = bbufs[grp & 1];
#pragma unroll
        for (int k = 0; k < 2; ++k) {
            if (k >= nc) break;
            const int t = c0 + k;
            const int jj = t - 9 * grp;
            const int shift = (jj / 3) * 58 + (jj % 3);
            const unsigned ab = abufs[t % NSTAGE_A];
            const unsigned bsh = b_off0 + shift * 128;
#pragma unroll
            for (int ks = 0; ks < 4; ++ks) {
                unsigned ar[8], br[16];
#pragma unroll
                for (int mt = 0; mt < 2; ++mt)
                    ldsm_x4(ar + mt * 4, ab + SWZ(a_off0 + mt * 2048 + ks * 32));
#pragma unroll
                for (int ntp = 0; ntp < 4; ++ntp)
                    ldsm_x4(br + ntp * 4, bb + SWZ(bsh + ntp * 2048 + ks * 32));
#pragma unroll
                for (int mt = 0; mt < 2; ++mt)
#pragma unroll
                    for (int nt = 0; nt < 8; ++nt) {
                        int bi = (nt >> 1) * 4 + (nt & 1) * 2;
                        mma_f16(acc + (mt * 8 + nt) * 4, ar + mt * 4,
                                br[bi], br[bi + 1]);
                    }
            }
        }
    }

    // --- epilogue: predicated direct stores ---
    const int qrow = lane >> 2;
    const int qc   = (lane & 3) * 2;
    const size_t ob = (size_t)b * COUT_ * HW;
#pragma unroll
    for (int mt = 0; mt < 2; ++mt) {
        const int mA = ocb * 128 + m0 + mt * 16 + qrow;
        const int mB = mA + 8;
#pragma unroll
        for (int nt = 0; nt < 8; ++nt) {
            const float* a4 = acc + (mt * 8 + nt) * 4;
            int p0 = n0 + n0w + nt * 8 + qc;
            int p1 = p0 + 1;
            int y0 = p0 / 58, x0 = p0 % 58;
            int y1 = p1 / 58, x1 = p1 % 58;
            bool v0 = (y0 < HH) && (x0 < WW);
            bool v1 = (y1 < HH) && (x1 < WW);
            if (v0) out[ob + ((size_t)mA * HH + y0) * WW + x0] = a4[0];
            if (v1) out[ob + ((size_t)mA * HH + y1) * WW + x1] = a4[1];
            if (v0) out[ob + ((size_t)mB * HH + y0) * WW + x0] = a4[2];
            if (v1) out[ob + ((size_t)mB * HH + y1) * WW + x1] = a4[3];
        }
    }
}

// ---------------------------------------------------------------------------
extern "C" void kernel_launch(void* const* d_in, const int* in_sizes, int n_in,
                              void* d_out, int out_size) {
    const float* x      = (const float*)d_in[0];
    const float* scores = (const float*)d_in[1];
    const float* weight = (const float*)d_in[2];
    const float* lora_A = (const float*)d_in[3];
    const float* lora_B = (const float*)d_in[4];
    float* out = (float*)d_out;

    cudaFuncSetAttribute(conv_mma_kernel,
                         cudaFuncAttributeMaxDynamicSharedMemorySize, SMEM_TOTAL);

    expert_kernel<<<1, 32>>>(scores);

    int total = E_ * COUT_ * M_PER_OC;          // 2,949,120
    abuild_kernel<<<total / 256, 256>>>(weight, lora_A, lora_B);

    dim3 xg(4, 58, B_);
    xprep_kernel<<<xg, 256>>>(x);

    dim3 cg(NTILES, 2, B_);
    conv_mma_kernel<<<cg, 512, SMEM_TOTAL>>>(out);
}

// round 17
// speedup vs baseline: 2.5857x; 1.5210x over previous
#include <cuda_runtime.h>
#include <cuda_fp16.h>
#include <cstdint>

// ---------------- problem constants ----------------
#define B_      32
#define E_      5
#define CIN_    256
#define COUT_   256
#define HH      56
#define WW      56
#define HW      (HH * WW)        // 3136
#define M_PER_OC 2304
#define NP      3364             // 58*58 padded pixels
#define KCH     36               // 4 groups x 9 shifts (fp16: K=2304)
#define NGRP    4
#define NTILES  13               // n tiles of 256 px
#define AK      2304             // A row length (fp16 elements)

// SMEM: 4 A-stages + 2 B super-tiles, 1 CTA/SM
#define A_TILE_B   16384         // 128 rows * 128B
#define NSTAGE_A   4
#define BSUP_ROWS  374           // 256 + max shift 118
#define BSUP_B     49152         // 384 rows * 128B (padded)
#define BBUF_OFF   (NSTAGE_A * A_TILE_B)          // 65536
#define SMEM_TOTAL (BBUF_OFF + 2 * BSUP_B)        // 163840 (160 KB)

typedef unsigned long long u64;

// ---------------- device globals ----------------
__device__ int g_expert[B_];
// A matrix: [e][ocb][128 oc][2304 k] fp16, k = (cq*9 + k1k2)*64 + cl
__device__ __half g_A[(size_t)E_ * 2 * 128 * AK];
// padded transposed input: [b][n 3364][c 256] fp16
__device__ __half g_xpt[(size_t)B_ * NP * 256];

// ---------------- helpers ----------------
__device__ __forceinline__ unsigned SWZ(unsigned off) {
    return off ^ ((off >> 3) & 0x70);
}

// L1-bypass fill: B super-tile / A stages have no L1 reuse (single smem landing)
__device__ __forceinline__ void cpa16(unsigned dst, const void* src, unsigned srcsize) {
    asm volatile("cp.async.cg.shared.global [%0], [%1], 16, %2;\n"
                 :: "r"(dst), "l"(src), "r"(srcsize) : "memory");
}

__device__ __forceinline__ void ldsm_x4(unsigned* r, unsigned addr) {
    asm volatile("ldmatrix.sync.aligned.m8n8.x4.shared.b16 {%0,%1,%2,%3}, [%4];"
                 : "=r"(r[0]), "=r"(r[1]), "=r"(r[2]), "=r"(r[3]) : "r"(addr));
}

__device__ __forceinline__ void mma_f16(float* d, const unsigned* a,
                                        unsigned b0, unsigned b1) {
    asm volatile(
        "mma.sync.aligned.m16n8k16.row.col.f32.f16.f16.f32 "
        "{%0,%1,%2,%3}, {%4,%5,%6,%7}, {%8,%9}, {%0,%1,%2,%3};"
        : "+f"(d[0]), "+f"(d[1]), "+f"(d[2]), "+f"(d[3])
        : "r"(a[0]), "r"(a[1]), "r"(a[2]), "r"(a[3]), "r"(b0), "r"(b1));
}

// ---------------------------------------------------------------------------
// Kernel 1: top-1 expert per sample
// ---------------------------------------------------------------------------
__global__ void expert_kernel(const float* __restrict__ scores) {
    int b = threadIdx.x;
    if (b < B_) {
        const float* s = scores + b * E_;
        float best = s[0];
        int bi = 0;
#pragma unroll
        for (int e = 1; e < E_; ++e) {
            float v = s[e];
            if (v > best) { best = v; bi = e; }
        }
        g_expert[b] = bi;
    }
}

// ---------------------------------------------------------------------------
// Kernel 2: build A (output-indexed -> fully coalesced 2B writes)
// out idx = ((e*2+ocb)*128 + ocl)*2304 + (cq*9+kk)*64 + cl
// ---------------------------------------------------------------------------
__global__ void abuild_kernel(const float* __restrict__ weight,
                              const float* __restrict__ lora_A,
                              const float* __restrict__ lora_B) {
    int t = blockIdx.x * blockDim.x + threadIdx.x;   // 5*2*128*2304
    int kidx   = t % AK;
    int rest   = t / AK;
    int ocl    = rest % 128;
    int slab   = rest / 128;
    int e      = slab >> 1;
    if (e >= E_) return;
    int ocb    = slab & 1;

    int cl = kidx & 63;
    int kq = kidx >> 6;          // 0..35
    int cq = kq / 9, kk = kq % 9;
    int ci = cq * 64 + cl;
    int m  = ci * 9 + kk;        // within-oc flat index
    int oc = ocb * 128 + ocl;

    int j = m / 768, v = m % 768;
    const float* Bp = lora_B + e * 9216 + (3 * oc + j) * 12;
    const float* Ap = lora_A + e * 9216;
    float acc = 0.f;
#pragma unroll
    for (int r = 0; r < 12; ++r) acc += Bp[r] * Ap[r * 768 + v];
    float val = weight[oc * M_PER_OC + m] + 4.0f * acc;

    g_A[(size_t)t] = __float2half(val);
}

// ---------------------------------------------------------------------------
// Kernel 3: padded, transposed fp16 input xp_t[b][n][c]
// ---------------------------------------------------------------------------
__global__ void xprep_kernel(const float* __restrict__ x) {
    __shared__ float tile[64 * 58];
    int cblk = blockIdx.x, y58 = blockIdx.y, b = blockIdx.z;
    int tid = threadIdx.x;
    int y = y58 - 1;
    if (y >= 0 && y < HH) {
        for (int idx = tid; idx < 64 * 58; idx += 256) {
            int c = idx / 58, px = idx % 58;
            int xx = px - 1;
            float v = 0.f;
            if (xx >= 0 && xx < WW)
                v = x[((size_t)(b * CIN_ + cblk * 64 + c)) * HW + y * WW + xx];
            tile[idx] = v;
        }
    } else {
        for (int idx = tid; idx < 64 * 58; idx += 256) tile[idx] = 0.f;
    }
    __syncthreads();
    __half* dst = g_xpt + ((size_t)b * NP + y58 * 58) * 256 + cblk * 64;
    for (int idx = tid; idx < 58 * 64; idx += 256) {
        int px = idx >> 6, c = idx & 63;
        dst[(size_t)px * 256 + c] = __float2half(tile[c * 58 + px]);
    }
}

// ---------------------------------------------------------------------------
// Loaders (256 threads)
// ---------------------------------------------------------------------------
__device__ __forceinline__ void load_A(int q, unsigned abuf,
                                       const __half* Abase, int tid) {
    int row = tid >> 1;                  // 128 rows, 2 threads/row
    int ub  = (tid & 1) * 4;
    const char* arow = (const char*)(Abase + (size_t)row * AK + q * 64);
#pragma unroll
    for (int u = 0; u < 4; ++u)
        cpa16(abuf + SWZ(row * 128 + (ub + u) * 16), arow + (ub + u) * 16, 16);
}

// load 1/6 slice (63 rows) of group gg's B super-tile
__device__ __forceinline__ void load_Bslice6(int gg, int j, unsigned bbuf,
                                             const __half* Bbase,
                                             int n0, int tid) {
    int c0 = gg * 64;
#pragma unroll
    for (int rep = 0; rep < 2; ++rep) {
        int idx = tid + rep * 256;
        if (idx < 63 * 8) {
            int r = j * 63 + (idx >> 3);
            if (r < BSUP_ROWS) {
                int n = n0 + r;
                bool ok = (n < NP);
                const char* src = ok ? (const char*)(Bbase + (size_t)n * 256 + c0)
                                     : (const char*)Bbase;
                unsigned sz = ok ? 16u : 0u;
                cpa16(bbuf + SWZ(r * 128 + (idx & 7) * 16), src + (idx & 7) * 16, sz);
            }
        }
    }
}

// load full B super-tile (prologue)
__device__ __forceinline__ void load_Bfull(int gg, unsigned bbuf,
                                           const __half* Bbase,
                                           int n0, int tid) {
    int c0 = gg * 64;
#pragma unroll
    for (int k = 0; k < 12; ++k) {
        int r = (tid >> 3) + k * 32;
        if (r < BSUP_ROWS) {
            int n = n0 + r;
            bool ok = (n < NP);
            const char* src = ok ? (const char*)(Bbase + (size_t)n * 256 + c0)
                                 : (const char*)Bbase;
            unsigned sz = ok ? 16u : 0u;
            cpa16(bbuf + SWZ(r * 128 + (tid & 7) * 16), src + (tid & 7) * 16, sz);
        }
    }
}

// ---------------------------------------------------------------------------
// Kernel 4: HMMA implicit-GEMM conv (fp16, K=2304). grid (13, 2, 32), 256 thr.
// CTA: 128 oc x 256 px. Warp grid 2(M)x4(N), warp tile 64x64 (min LDSM traffic).
// 4-stage A pipeline (distance 3), B super-tile double-buffered, .cg fills.
// ---------------------------------------------------------------------------
__global__ __launch_bounds__(256, 1)
void conv_mma_kernel(float* __restrict__ out) {
    extern __shared__ __align__(1024) char smem[];
    const unsigned sbase = (unsigned)__cvta_generic_to_shared(smem);
    const int tid  = threadIdx.x;
    const int lane = tid & 31, wid = tid >> 5;
    const int n0   = blockIdx.x * 256;
    const int ocb  = blockIdx.y;
    const int b    = blockIdx.z;
    const int e    = g_expert[b];

    const __half* Abase = g_A + (size_t)(e * 2 + ocb) * 128 * AK;
    const __half* Bbase = g_xpt + (size_t)b * NP * 256;

    unsigned abufs[NSTAGE_A];
#pragma unroll
    for (int i = 0; i < NSTAGE_A; ++i) abufs[i] = sbase + i * A_TILE_B;
    const unsigned bbufs[2] = { sbase + BBUF_OFF, sbase + BBUF_OFF + BSUP_B };

    float acc[128];
#pragma unroll
    for (int i = 0; i < 128; ++i) acc[i] = 0.f;

    // warp / lane geometry: 2(M) x 4(N) warps, warp tile 64(M) x 64(N)
    const int wm = wid & 1, wn = wid >> 1;
    const int m0 = wm * 64, n0w = wn * 64;
    const int g  = lane >> 3, lr = lane & 7;
    const unsigned a_off0 = (unsigned)((m0 + (g & 1) * 8 + lr) * 128 + (g >> 1) * 16);
    const unsigned b_off0 = (unsigned)((n0w + (g >> 1) * 8 + lr) * 128 + (g & 1) * 16);

    // prologue: c0 = {Bfull(g0), A0}; c1 = {A1}; c2 = {A2}
    load_Bfull(0, bbufs[0], Bbase, n0, tid);
    load_A(0, abufs[0], Abase, tid);
    asm volatile("cp.async.commit_group;" ::: "memory");
    load_A(1, abufs[1], Abase, tid);
    asm volatile("cp.async.commit_group;" ::: "memory");
    load_A(2, abufs[2], Abase, tid);
    asm volatile("cp.async.commit_group;" ::: "memory");

    for (int t = 0; t < KCH; ++t) {
        const int grp = t / 9;
        const int j   = t - grp * 9;
        const int shift = (j / 3) * 58 + (j % 3);

        if (t < KCH - 2)
            asm volatile("cp.async.wait_group 2;" ::: "memory");
        else if (t == KCH - 2)
            asm volatile("cp.async.wait_group 1;" ::: "memory");
        else
            asm volatile("cp.async.wait_group 0;" ::: "memory");
        __syncthreads();

        // prefetch A(t+3); B slices of next group issued early (j=0..5)
        if (t + 3 < KCH) {
            load_A(t + 3, abufs[(t + 3) & 3], Abase, tid);
            if (j < 6 && grp + 1 < NGRP)
                load_Bslice6(grp + 1, j, bbufs[(grp + 1) & 1], Bbase, n0, tid);
            asm volatile("cp.async.commit_group;" ::: "memory");
        }

        const unsigned ab = abufs[t & 3];
        const unsigned bb = bbufs[grp & 1];
        const unsigned bsh = b_off0 + shift * 128;
#pragma unroll
        for (int ks = 0; ks < 4; ++ks) {
            unsigned ar[16], br[16];
#pragma unroll
            for (int mt = 0; mt < 4; ++mt)
                ldsm_x4(ar + mt * 4, ab + SWZ(a_off0 + mt * 2048 + ks * 32));
#pragma unroll
            for (int ntp = 0; ntp < 4; ++ntp)
                ldsm_x4(br + ntp * 4, bb + SWZ(bsh + ntp * 2048 + ks * 32));
#pragma unroll
            for (int mt = 0; mt < 4; ++mt)
#pragma unroll
                for (int nt = 0; nt < 8; ++nt) {
                    int bi = (nt >> 1) * 4 + (nt & 1) * 2;
                    mma_f16(acc + (mt * 8 + nt) * 4, ar + mt * 4,
                            br[bi], br[bi + 1]);
                }
        }
    }

    // --- epilogue: predicated direct stores (y/x hoisted per nt) ---
    const int qrow = lane >> 2;
    const int qc   = (lane & 3) * 2;
    const size_t ob = (size_t)b * COUT_ * HW;
    int ylist[8], xlist[8];
    bool v0l[8], v1l[8];
#pragma unroll
    for (int nt = 0; nt < 8; ++nt) {
        int p0 = n0 + n0w + nt * 8 + qc;
        int y0 = p0 / 58, x0 = p0 % 58;
        int y1 = y0, x1 = x0 + 1;
        if (x1 == 58) { y1 += 1; x1 = 0; }
        ylist[nt] = y0; xlist[nt] = x0;
        v0l[nt] = (y0 < HH) && (x0 < WW);
        v1l[nt] = (y1 < HH) && (x1 < WW);
    }
#pragma unroll
    for (int mt = 0; mt < 4; ++mt) {
        const int mA = ocb * 128 + m0 + mt * 16 + qrow;
        const int mB = mA + 8;
#pragma unroll
        for (int nt = 0; nt < 8; ++nt) {
            const float* a4 = acc + (mt * 8 + nt) * 4;
            int y0 = ylist[nt], x0 = xlist[nt];
            if (v0l[nt]) {
                out[ob + ((size_t)mA * HH + y0) * WW + x0] = a4[0];
                out[ob + ((size_t)mB * HH + y0) * WW + x0] = a4[2];
            }
            if (v1l[nt]) {
                int y1 = y0, x1 = x0 + 1;
                if (x1 == 58) { y1 += 1; x1 = 0; }
                out[ob + ((size_t)mA * HH + y1) * WW + x1] = a4[1];
                out[ob + ((size_t)mB * HH + y1) * WW + x1] = a4[3];
            }
        }
    }
}

// ---------------------------------------------------------------------------
extern "C" void kernel_launch(void* const* d_in, const int* in_sizes, int n_in,
                              void* d_out, int out_size) {
    const float* x      = (const float*)d_in[0];
    const float* scores = (const float*)d_in[1];
    const float* weight = (const float*)d_in[2];
    const float* lora_A = (const float*)d_in[3];
    const float* lora_B = (const float*)d_in[4];
    float* out = (float*)d_out;

    cudaFuncSetAttribute(conv_mma_kernel,
                         cudaFuncAttributeMaxDynamicSharedMemorySize, SMEM_TOTAL);

    expert_kernel<<<1, 32>>>(scores);

    int total = E_ * 2 * 128 * AK;              // 2,949,120
    abuild_kernel<<<total / 256, 256>>>(weight, lora_A, lora_B);

    dim3 xg(4, 58, B_);
    xprep_kernel<<<xg, 256>>>(x);

    dim3 cg(NTILES, 2, B_);
    conv_mma_kernel<<<cg, 256, SMEM_TOTAL>>>(out);
}